// round 14
// baseline (speedup 1.0000x reference)
#include <cuda_runtime.h>
#include <cuda_fp16.h>
#include <mma.h>
#include <math.h>
#include <stdint.h>

using namespace nvcuda;

// Linear attention, wmma m16n16k16 + 3xFP16 hi/lo splitting.
// R14: 128x128 block tiles with 512 threads (16 warps, 4x4), warp tile 32x32
// so acc stays 32 regs/thread (no spill). Halves A-operand DRAM re-reads vs
// the 64-wide tiles of R13. BK=32, 2-stage cp.async, dynamic smem.
//   conv:  xh/xl = split(x);  wh/wl = split(256*W)
//   proj:  acc = x @ 256W;  qh/ql = split(exp(acc/256)/16) = split(16*q'')
//   zc  :  zc[l] = 4096 / (16*sum(qh+ql) + 1e-8)
//   kv  :  acc = (16k'')^T @ x = kv/16;  kvh/kvl = split(acc/16) = split(kv/256)
//   num :  acc = (16q'') @ (kv/256) = q'*kv/4096;  out = acc * zc[l]

#define BATCH 8
#define LSEQ  4096
#define DDIM  1024
#define EDIM  256
#define BL    (BATCH * LSEQ)
#define SPA   40    // A row-major tile pitch: 32 data + 8 pad halves
#define SPB   136   // B tile pitch: 128 data + 8 pad halves
#define SPK   136   // kv A col-major tile pitch

// dynamic smem layout (bytes)
#define A_HL    (128 * SPA * 2)          // 10240
#define ASTAGE  (2 * A_HL)               // 20480
#define SBOFF   (2 * ASTAGE)             // 40960
#define B_HL    (32 * SPB * 2)           // 8704
#define BSTAGE  (2 * B_HL)               // 17408
#define SMEM_PN (SBOFF + 2 * BSTAGE)     // 75776
#define AK_HL   (32 * SPK * 2)           // 8704
#define AKSTAGE (2 * AK_HL)              // 17408
#define SBOFF_K (2 * AKSTAGE)            // 34816
#define SMEM_KV (SBOFF_K + 2 * BSTAGE)   // 69632

// ---- scratch ----
__device__ __align__(16) __half g_xh[(size_t)BL * DDIM];   // [l][d]
__device__ __align__(16) __half g_xl[(size_t)BL * DDIM];
__device__ __align__(16) __half g_wqh[DDIM * EDIM];        // [d][e], 256W
__device__ __align__(16) __half g_wql[DDIM * EDIM];
__device__ __align__(16) __half g_wkh[DDIM * EDIM];
__device__ __align__(16) __half g_wkl[DDIM * EDIM];
__device__ __align__(16) __half g_qh[(size_t)BL * EDIM];   // [l][e], 16q''
__device__ __align__(16) __half g_ql[(size_t)BL * EDIM];
__device__ __align__(16) __half g_kh[(size_t)BL * EDIM];
__device__ __align__(16) __half g_kl[(size_t)BL * EDIM];
__device__ __align__(16) __half g_kvh[(size_t)BATCH * EDIM * DDIM];  // [b][e][d]
__device__ __align__(16) __half g_kvl[(size_t)BATCH * EDIM * DDIM];
__device__ float g_zc[BL];

// ---------------- helpers ----------------
__device__ __forceinline__ void split2(float x, __half& h, __half& l) {
    h = __float2half_rn(x);
    l = __float2half_rn(x - __half2float(h));
}
__device__ __forceinline__ uint32_t sptr(const void* p) {
    return (uint32_t)__cvta_generic_to_shared(p);
}
#define CP16(dst, src) \
    asm volatile("cp.async.cg.shared.global [%0], [%1], 16;" :: "r"(dst), "l"(src))
#define CP_COMMIT() asm volatile("cp.async.commit_group;")
#define CP_WAIT1()  asm volatile("cp.async.wait_group 1;")
#define CP_WAIT0()  asm volatile("cp.async.wait_group 0;")

#define ACC_DECL                                                               \
    wmma::fragment<wmma::accumulator, 16, 16, 16, float> acc[2][2];            \
    _Pragma("unroll") for (int mi = 0; mi < 2; mi++)                           \
    _Pragma("unroll") for (int nj = 0; nj < 2; nj++)                           \
        wmma::fill_fragment(acc[mi][nj], 0.0f)

// A row-major ([m][32k] pitch SPA), B ([32k][128n] pitch SPB); 2 k-steps.
__device__ __forceinline__ void mma_rowA32(
    const __half* Ah, const __half* Al, const __half* Bh, const __half* Bl,
    wmma::fragment<wmma::accumulator, 16, 16, 16, float> acc[2][2],
    int warpM, int warpN)
{
#pragma unroll
    for (int kk = 0; kk < 32; kk += 16) {
        wmma::fragment<wmma::matrix_b, 16, 16, 16, __half, wmma::row_major> bh[2], bl[2];
#pragma unroll
        for (int nj = 0; nj < 2; nj++) {
            int n0 = warpN * 32 + nj * 16;
            wmma::load_matrix_sync(bh[nj], Bh + kk * SPB + n0, SPB);
            wmma::load_matrix_sync(bl[nj], Bl + kk * SPB + n0, SPB);
        }
#pragma unroll
        for (int mi = 0; mi < 2; mi++) {
            int m0 = warpM * 32 + mi * 16;
            wmma::fragment<wmma::matrix_a, 16, 16, 16, __half, wmma::row_major> ah, al;
            wmma::load_matrix_sync(ah, Ah + m0 * SPA + kk, SPA);
            wmma::load_matrix_sync(al, Al + m0 * SPA + kk, SPA);
#pragma unroll
            for (int nj = 0; nj < 2; nj++) {
                wmma::mma_sync(acc[mi][nj], ah, bh[nj], acc[mi][nj]);
                wmma::mma_sync(acc[mi][nj], ah, bl[nj], acc[mi][nj]);
                wmma::mma_sync(acc[mi][nj], al, bh[nj], acc[mi][nj]);
            }
        }
    }
}
// A col-major ([32k][128m] pitch SPK)
__device__ __forceinline__ void mma_colA32(
    const __half* Ah, const __half* Al, const __half* Bh, const __half* Bl,
    wmma::fragment<wmma::accumulator, 16, 16, 16, float> acc[2][2],
    int warpM, int warpN)
{
#pragma unroll
    for (int kk = 0; kk < 32; kk += 16) {
        wmma::fragment<wmma::matrix_b, 16, 16, 16, __half, wmma::row_major> bh[2], bl[2];
#pragma unroll
        for (int nj = 0; nj < 2; nj++) {
            int n0 = warpN * 32 + nj * 16;
            wmma::load_matrix_sync(bh[nj], Bh + kk * SPB + n0, SPB);
            wmma::load_matrix_sync(bl[nj], Bl + kk * SPB + n0, SPB);
        }
#pragma unroll
        for (int mi = 0; mi < 2; mi++) {
            int m0 = warpM * 32 + mi * 16;
            wmma::fragment<wmma::matrix_a, 16, 16, 16, __half, wmma::col_major> ah, al;
            wmma::load_matrix_sync(ah, Ah + kk * SPK + m0, SPK);
            wmma::load_matrix_sync(al, Al + kk * SPK + m0, SPK);
#pragma unroll
            for (int nj = 0; nj < 2; nj++) {
                wmma::mma_sync(acc[mi][nj], ah, bh[nj], acc[mi][nj]);
                wmma::mma_sync(acc[mi][nj], ah, bl[nj], acc[mi][nj]);
                wmma::mma_sync(acc[mi][nj], al, bh[nj], acc[mi][nj]);
            }
        }
    }
}

// ---------------- convert kernels ----------------
__global__ __launch_bounds__(256) void conv_x(const float4* __restrict__ x) {
    size_t i = (size_t)blockIdx.x * 256 + threadIdx.x;   // BL*DDIM/4
    float4 v = x[i];
    __half h[4], l[4];
    split2(v.x, h[0], l[0]); split2(v.y, h[1], l[1]);
    split2(v.z, h[2], l[2]); split2(v.w, h[3], l[3]);
    ((uint2*)g_xh)[i] = *(uint2*)h;
    ((uint2*)g_xl)[i] = *(uint2*)l;
}
__global__ __launch_bounds__(256) void conv_w(const float4* __restrict__ qw,
                                              const float4* __restrict__ kw) {
    size_t i = (size_t)blockIdx.x * 256 + threadIdx.x;   // DDIM*EDIM/4
    const float4* W = blockIdx.y ? kw : qw;
    __half* oh = blockIdx.y ? g_wkh : g_wqh;
    __half* ol = blockIdx.y ? g_wkl : g_wql;
    float4 v = W[i];
    __half h[4], l[4];
    split2(v.x * 256.0f, h[0], l[0]); split2(v.y * 256.0f, h[1], l[1]);
    split2(v.z * 256.0f, h[2], l[2]); split2(v.w * 256.0f, h[3], l[3]);
    ((uint2*)oh)[i] = *(uint2*)h;
    ((uint2*)ol)[i] = *(uint2*)l;
}

// ---------------- proj: grid (EDIM/128=2, BL/128=256, 2), 512 thr ----------
__global__ __launch_bounds__(512, 1) void proj_kernel()
{
    extern __shared__ __align__(16) char dsm[];
    const int tid = threadIdx.x, lane = tid & 31, wid = tid >> 5;
    const int warpM = wid >> 2, warpN = wid & 3;
    const int mBase = blockIdx.y * 128, nBase = blockIdx.x * 128;
    const __half* Ah = g_xh + (size_t)mBase * DDIM;           // [m][k]
    const __half* Al = g_xl + (size_t)mBase * DDIM;
    const __half* Bh = (blockIdx.z ? g_wkh : g_wqh) + nBase;  // [k][n]
    const __half* Bl = (blockIdx.z ? g_wkl : g_wql) + nBase;
    __half* Oh = blockIdx.z ? g_kh : g_qh;
    __half* Ol = blockIdx.z ? g_kl : g_ql;

    // A: 128x32 halves = 512 chunks, 1/thread.  B: 32x128 = 512 chunks.
    const int am = tid >> 2, ac = (tid & 3) * 8;
    const int bk = tid >> 4, bn = (tid & 15) * 8;
    const uint32_t sbase = sptr(dsm);
    const uint32_t dA = sbase + (am * SPA + ac) * 2;
    const uint32_t dB = sbase + SBOFF + (bk * SPB + bn) * 2;

    ACC_DECL;
    const int NK = DDIM / 32;
#define PROJ_CP(s, k0)                                                         \
    do {                                                                       \
        CP16(dA + (s) * ASTAGE,         Ah + (size_t)am * DDIM + (k0) + ac);   \
        CP16(dA + (s) * ASTAGE + A_HL,  Al + (size_t)am * DDIM + (k0) + ac);   \
        CP16(dB + (s) * BSTAGE,         Bh + (size_t)((k0) + bk) * EDIM + bn); \
        CP16(dB + (s) * BSTAGE + B_HL,  Bl + (size_t)((k0) + bk) * EDIM + bn); \
        CP_COMMIT();                                                           \
    } while (0)

    PROJ_CP(0, 0);
    for (int t = 0; t < NK; t++) {
        if (t + 1 < NK) { PROJ_CP((t + 1) & 1, (t + 1) * 32); CP_WAIT1(); }
        else            { CP_WAIT0(); }
        __syncthreads();
        int s = t & 1;
        mma_rowA32((const __half*)(dsm + s * ASTAGE),
                   (const __half*)(dsm + s * ASTAGE + A_HL),
                   (const __half*)(dsm + SBOFF + s * BSTAGE),
                   (const __half*)(dsm + SBOFF + s * BSTAGE + B_HL),
                   acc, warpM, warpN);
        __syncthreads();
    }
#undef PROJ_CP

    // epilogue: v = exp(acc/256)/16, split hi/lo, coalesced write
    float* stage = reinterpret_cast<float*>(dsm) + wid * 256;
    const float ie = 1.0f / 256.0f;
    const int r = lane >> 1, c0 = (lane & 1) * 8;
#pragma unroll
    for (int mi = 0; mi < 2; mi++)
#pragma unroll
        for (int nj = 0; nj < 2; nj++) {
            wmma::store_matrix_sync(stage, acc[mi][nj], 16, wmma::mem_row_major);
            __syncwarp();
            int rg = mBase + warpM * 32 + mi * 16 + r;
            int cg = nBase + warpN * 32 + nj * 16 + c0;
            __half hb[8], lb[8];
#pragma unroll
            for (int j = 0; j < 8; j++) {
                float v = expf(stage[r * 16 + c0 + j] * ie) * 0.0625f;
                split2(v, hb[j], lb[j]);
            }
            *(uint4*)(Oh + (size_t)rg * EDIM + cg) = *(uint4*)hb;
            *(uint4*)(Ol + (size_t)rg * EDIM + cg) = *(uint4*)lb;
            __syncwarp();
        }
}

// ---------------- zc: one warp per row ----------------
__global__ __launch_bounds__(256) void zc_kernel()
{
    int row = (int)((blockIdx.x * 256 + threadIdx.x) >> 5);
    int lane = threadIdx.x & 31;
    const __half2* ph = (const __half2*)(g_qh + (size_t)row * EDIM);
    const __half2* pl = (const __half2*)(g_ql + (size_t)row * EDIM);
    float s = 0.0f;
#pragma unroll
    for (int i = 0; i < 4; i++) {
        float2 h = __half22float2(ph[lane + 32 * i]);
        float2 l = __half22float2(pl[lane + 32 * i]);
        s += (h.x + h.y) + (l.x + l.y);
    }
#pragma unroll
    for (int o = 16; o; o >>= 1) s += __shfl_xor_sync(0xffffffffu, s, o);
    if (lane == 0) g_zc[row] = 4096.0f / (16.0f * s + 1e-8f);
}

// ---------------- kv: grid (DDIM/128=8, EDIM/128=2, 8), 512 thr ------------
__global__ __launch_bounds__(512, 1) void kv_kernel()
{
    extern __shared__ __align__(16) char dsm[];
    const int tid = threadIdx.x, lane = tid & 31, wid = tid >> 5;
    const int warpM = wid >> 2, warpN = wid & 3;
    const int b = blockIdx.z;
    const int mBase = blockIdx.y * 128;   // e
    const int nBase = blockIdx.x * 128;   // d
    const __half* Ah = g_kh + (size_t)b * LSEQ * EDIM + mBase;  // [k=l][m=e]
    const __half* Al = g_kl + (size_t)b * LSEQ * EDIM + mBase;
    const __half* Bh = g_xh + (size_t)b * LSEQ * DDIM + nBase;  // [k=l][n=d]
    const __half* Bl = g_xl + (size_t)b * LSEQ * DDIM + nBase;

    const int ak = tid >> 4, an = (tid & 15) * 8;   // A 32x128
    const int bk = tid >> 4, bn = (tid & 15) * 8;   // B 32x128
    const uint32_t sbase = sptr(dsm);
    const uint32_t dA = sbase + (ak * SPK + an) * 2;
    const uint32_t dB = sbase + SBOFF_K + (bk * SPB + bn) * 2;

    ACC_DECL;
    const int NK = LSEQ / 32;
#define KV_CP(s, k0)                                                           \
    do {                                                                       \
        CP16(dA + (s) * AKSTAGE,         Ah + (size_t)((k0) + ak) * EDIM + an); \
        CP16(dA + (s) * AKSTAGE + AK_HL, Al + (size_t)((k0) + ak) * EDIM + an); \
        CP16(dB + (s) * BSTAGE,          Bh + (size_t)((k0) + bk) * DDIM + bn); \
        CP16(dB + (s) * BSTAGE + B_HL,   Bl + (size_t)((k0) + bk) * DDIM + bn); \
        CP_COMMIT();                                                           \
    } while (0)

    KV_CP(0, 0);
    for (int t = 0; t < NK; t++) {
        if (t + 1 < NK) { KV_CP((t + 1) & 1, (t + 1) * 32); CP_WAIT1(); }
        else            { CP_WAIT0(); }
        __syncthreads();
        int s = t & 1;
        mma_colA32((const __half*)(dsm + s * AKSTAGE),
                   (const __half*)(dsm + s * AKSTAGE + AK_HL),
                   (const __half*)(dsm + SBOFF_K + s * BSTAGE),
                   (const __half*)(dsm + SBOFF_K + s * BSTAGE + B_HL),
                   acc, warpM, warpN);
        __syncthreads();
    }
#undef KV_CP

    // epilogue: kvh/kvl = split(acc/16) = split(kv/256)
    float* stage = reinterpret_cast<float*>(dsm) + wid * 256;
    __half* Oh = g_kvh + (size_t)b * EDIM * DDIM;
    __half* Ol = g_kvl + (size_t)b * EDIM * DDIM;
    const int r = lane >> 1, c0 = (lane & 1) * 8;
#pragma unroll
    for (int mi = 0; mi < 2; mi++)
#pragma unroll
        for (int nj = 0; nj < 2; nj++) {
            wmma::store_matrix_sync(stage, acc[mi][nj], 16, wmma::mem_row_major);
            __syncwarp();
            int rg = mBase + warpM * 32 + mi * 16 + r;
            int cg = nBase + warpN * 32 + nj * 16 + c0;
            __half hb[8], lb[8];
#pragma unroll
            for (int j = 0; j < 8; j++)
                split2(stage[r * 16 + c0 + j] * 0.0625f, hb[j], lb[j]);
            *(uint4*)(Oh + (size_t)rg * DDIM + cg) = *(uint4*)hb;
            *(uint4*)(Ol + (size_t)rg * DDIM + cg) = *(uint4*)lb;
            __syncwarp();
        }
}

// ---------------- num: grid (8, 32, 8), 512 thr ----------------
__global__ __launch_bounds__(512, 1) void num_kernel(float* __restrict__ out)
{
    extern __shared__ __align__(16) char dsm[];
    const int tid = threadIdx.x, lane = tid & 31, wid = tid >> 5;
    const int warpM = wid >> 2, warpN = wid & 3;
    const int b = blockIdx.z;
    const int mBase = blockIdx.y * 128;   // l
    const int nBase = blockIdx.x * 128;   // d
    const __half* Ah = g_qh + ((size_t)b * LSEQ + mBase) * EDIM;  // [m=l][k=e]
    const __half* Al = g_ql + ((size_t)b * LSEQ + mBase) * EDIM;
    const __half* Bh = g_kvh + (size_t)b * EDIM * DDIM + nBase;   // [k=e][n=d]
    const __half* Bl = g_kvl + (size_t)b * EDIM * DDIM + nBase;

    const int am = tid >> 2, ac = (tid & 3) * 8;
    const int bk = tid >> 4, bn = (tid & 15) * 8;
    const uint32_t sbase = sptr(dsm);
    const uint32_t dA = sbase + (am * SPA + ac) * 2;
    const uint32_t dB = sbase + SBOFF + (bk * SPB + bn) * 2;

    ACC_DECL;
    const int NK = EDIM / 32;
#define NUM_CP(s, k0)                                                          \
    do {                                                                       \
        CP16(dA + (s) * ASTAGE,         Ah + (size_t)am * EDIM + (k0) + ac);   \
        CP16(dA + (s) * ASTAGE + A_HL,  Al + (size_t)am * EDIM + (k0) + ac);   \
        CP16(dB + (s) * BSTAGE,         Bh + (size_t)((k0) + bk) * DDIM + bn); \
        CP16(dB + (s) * BSTAGE + B_HL,  Bl + (size_t)((k0) + bk) * DDIM + bn); \
        CP_COMMIT();                                                           \
    } while (0)

    NUM_CP(0, 0);
    for (int t = 0; t < NK; t++) {
        if (t + 1 < NK) { NUM_CP((t + 1) & 1, (t + 1) * 32); CP_WAIT1(); }
        else            { CP_WAIT0(); }
        __syncthreads();
        int s = t & 1;
        mma_rowA32((const __half*)(dsm + s * ASTAGE),
                   (const __half*)(dsm + s * ASTAGE + A_HL),
                   (const __half*)(dsm + SBOFF + s * BSTAGE),
                   (const __half*)(dsm + SBOFF + s * BSTAGE + B_HL),
                   acc, warpM, warpN);
        __syncthreads();
    }
#undef NUM_CP

    // epilogue: out = acc * zc[row]
    float* stage = reinterpret_cast<float*>(dsm) + wid * 256;
    float* O = out + (size_t)b * LSEQ * DDIM;
    const int r = lane >> 1, c0 = (lane & 1) * 8;
#pragma unroll
    for (int mi = 0; mi < 2; mi++)
#pragma unroll
        for (int nj = 0; nj < 2; nj++) {
            wmma::store_matrix_sync(stage, acc[mi][nj], 16, wmma::mem_row_major);
            __syncwarp();
            int rg = mBase + warpM * 32 + mi * 16 + r;
            int cg = nBase + warpN * 32 + nj * 16 + c0;
            float zc = g_zc[b * LSEQ + rg];
            float ob[8];
#pragma unroll
            for (int j = 0; j < 8; j++)
                ob[j] = stage[r * 16 + c0 + j] * zc;
            *(float4*)(O + (size_t)rg * DDIM + cg)     = *(float4*)&ob[0];
            *(float4*)(O + (size_t)rg * DDIM + cg + 4) = *(float4*)&ob[4];
            __syncwarp();
        }
}

// ---------------- launch ----------------
extern "C" void kernel_launch(void* const* d_in, const int* in_sizes, int n_in,
                              void* d_out, int out_size)
{
    const float* x  = (const float*)d_in[0];
    const float* qw = (const float*)d_in[1];
    const float* kw = (const float*)d_in[2];
    float* out = (float*)d_out;

    cudaFuncSetAttribute(proj_kernel, cudaFuncAttributeMaxDynamicSharedMemorySize, SMEM_PN);
    cudaFuncSetAttribute(kv_kernel,   cudaFuncAttributeMaxDynamicSharedMemorySize, SMEM_KV);
    cudaFuncSetAttribute(num_kernel,  cudaFuncAttributeMaxDynamicSharedMemorySize, SMEM_PN);

    conv_x<<<(int)((size_t)BL * DDIM / 4 / 256), 256>>>((const float4*)x);
    conv_w<<<dim3(DDIM * EDIM / 4 / 256, 2), 256>>>((const float4*)qw,
                                                    (const float4*)kw);
    proj_kernel<<<dim3(EDIM / 128, BL / 128, 2), 512, SMEM_PN>>>();
    zc_kernel<<<BL / 8, 256>>>();
    kv_kernel<<<dim3(DDIM / 128, EDIM / 128, BATCH), 512, SMEM_KV>>>();
    num_kernel<<<dim3(DDIM / 128, LSEQ / 128, BATCH), 512, SMEM_PN>>>(out);
}

// round 15
// speedup vs baseline: 1.0593x; 1.0593x over previous
#include <cuda_runtime.h>
#include <cuda_fp16.h>
#include <mma.h>
#include <math.h>
#include <stdint.h>

using namespace nvcuda;

// Linear attention, wmma m16n16k16 + 3xFP16 hi/lo splitting.
// R15 = R13 base (128x64 tiles, 256 thr, 2 CTA/SM, BK=32, dynamic smem)
// + 3-stage cp.async pipeline with ONE __syncthreads per K-chunk
// (copy into stage t+2 issued right after the barrier, overlapping the mma).
//   conv:  xh/xl = split(x);  wh/wl = split(256*W)
//   proj:  acc = x @ 256W;  qh/ql = split(exp(acc/256)/16) = split(16*q'')
//   zc  :  zc[l] = 4096 / (16*sum(qh+ql) + 1e-8)
//   kv  :  acc = (16k'')^T @ x = kv/16;  kvh/kvl = split(acc/16) = split(kv/256)
//   num :  acc = (16q'') @ (kv/256) = q'*kv/4096;  out = acc * zc[l]

#define BATCH 8
#define LSEQ  4096
#define DDIM  1024
#define EDIM  256
#define BL    (BATCH * LSEQ)
#define SPA   40    // A row-major tile pitch: 32 data + 8 pad halves
#define SPB   72    // B tile pitch: 64 data + 8 pad halves
#define SPK   136   // kv A col-major tile pitch: 128 data + 8 pad halves

// dynamic smem layout (bytes), 3 stages
#define A_HL    (128 * SPA * 2)          // 10240
#define ASTAGE  (2 * A_HL)               // 20480
#define SBOFF   (3 * ASTAGE)             // 61440
#define B_HL    (32 * SPB * 2)           // 4608
#define BSTAGE  (2 * B_HL)               // 9216
#define SMEM_PN (SBOFF + 3 * BSTAGE)     // 89088
#define AK_HL   (32 * SPK * 2)           // 8704
#define AKSTAGE (2 * AK_HL)              // 17408
#define SBOFF_K (3 * AKSTAGE)            // 52224
#define SMEM_KV (SBOFF_K + 3 * BSTAGE)   // 79872

// ---- scratch ----
__device__ __align__(16) __half g_xh[(size_t)BL * DDIM];   // [l][d]
__device__ __align__(16) __half g_xl[(size_t)BL * DDIM];
__device__ __align__(16) __half g_wqh[DDIM * EDIM];        // [d][e], 256W
__device__ __align__(16) __half g_wql[DDIM * EDIM];
__device__ __align__(16) __half g_wkh[DDIM * EDIM];
__device__ __align__(16) __half g_wkl[DDIM * EDIM];
__device__ __align__(16) __half g_qh[(size_t)BL * EDIM];   // [l][e], 16q''
__device__ __align__(16) __half g_ql[(size_t)BL * EDIM];
__device__ __align__(16) __half g_kh[(size_t)BL * EDIM];
__device__ __align__(16) __half g_kl[(size_t)BL * EDIM];
__device__ __align__(16) __half g_kvh[(size_t)BATCH * EDIM * DDIM];  // [b][e][d]
__device__ __align__(16) __half g_kvl[(size_t)BATCH * EDIM * DDIM];
__device__ float g_zc[BL];

// ---------------- helpers ----------------
__device__ __forceinline__ void split2(float x, __half& h, __half& l) {
    h = __float2half_rn(x);
    l = __float2half_rn(x - __half2float(h));
}
__device__ __forceinline__ uint32_t sptr(const void* p) {
    return (uint32_t)__cvta_generic_to_shared(p);
}
#define CP16(dst, src) \
    asm volatile("cp.async.cg.shared.global [%0], [%1], 16;" :: "r"(dst), "l"(src))
#define CP_COMMIT() asm volatile("cp.async.commit_group;")
#define CP_WAIT1()  asm volatile("cp.async.wait_group 1;")
#define CP_WAIT0()  asm volatile("cp.async.wait_group 0;")

#define ACC_DECL                                                               \
    wmma::fragment<wmma::accumulator, 16, 16, 16, float> acc[2][2];            \
    _Pragma("unroll") for (int mi = 0; mi < 2; mi++)                           \
    _Pragma("unroll") for (int nj = 0; nj < 2; nj++)                           \
        wmma::fill_fragment(acc[mi][nj], 0.0f)

// A row-major ([m][32k] pitch SPA), B ([32k][64n] pitch SPB); 2 k-steps.
__device__ __forceinline__ void mma_rowA32(
    const __half* Ah, const __half* Al, const __half* Bh, const __half* Bl,
    wmma::fragment<wmma::accumulator, 16, 16, 16, float> acc[2][2],
    int warpM, int warpN)
{
#pragma unroll
    for (int kk = 0; kk < 32; kk += 16) {
        wmma::fragment<wmma::matrix_b, 16, 16, 16, __half, wmma::row_major> bh[2], bl[2];
#pragma unroll
        for (int nj = 0; nj < 2; nj++) {
            int n0 = warpN * 32 + nj * 16;
            wmma::load_matrix_sync(bh[nj], Bh + kk * SPB + n0, SPB);
            wmma::load_matrix_sync(bl[nj], Bl + kk * SPB + n0, SPB);
        }
#pragma unroll
        for (int mi = 0; mi < 2; mi++) {
            int m0 = warpM * 32 + mi * 16;
            wmma::fragment<wmma::matrix_a, 16, 16, 16, __half, wmma::row_major> ah, al;
            wmma::load_matrix_sync(ah, Ah + m0 * SPA + kk, SPA);
            wmma::load_matrix_sync(al, Al + m0 * SPA + kk, SPA);
#pragma unroll
            for (int nj = 0; nj < 2; nj++) {
                wmma::mma_sync(acc[mi][nj], ah, bh[nj], acc[mi][nj]);
                wmma::mma_sync(acc[mi][nj], ah, bl[nj], acc[mi][nj]);
                wmma::mma_sync(acc[mi][nj], al, bh[nj], acc[mi][nj]);
            }
        }
    }
}
// A col-major ([32k][128m] pitch SPK)
__device__ __forceinline__ void mma_colA32(
    const __half* Ah, const __half* Al, const __half* Bh, const __half* Bl,
    wmma::fragment<wmma::accumulator, 16, 16, 16, float> acc[2][2],
    int warpM, int warpN)
{
#pragma unroll
    for (int kk = 0; kk < 32; kk += 16) {
        wmma::fragment<wmma::matrix_b, 16, 16, 16, __half, wmma::row_major> bh[2], bl[2];
#pragma unroll
        for (int nj = 0; nj < 2; nj++) {
            int n0 = warpN * 32 + nj * 16;
            wmma::load_matrix_sync(bh[nj], Bh + kk * SPB + n0, SPB);
            wmma::load_matrix_sync(bl[nj], Bl + kk * SPB + n0, SPB);
        }
#pragma unroll
        for (int mi = 0; mi < 2; mi++) {
            int m0 = warpM * 32 + mi * 16;
            wmma::fragment<wmma::matrix_a, 16, 16, 16, __half, wmma::col_major> ah, al;
            wmma::load_matrix_sync(ah, Ah + kk * SPK + m0, SPK);
            wmma::load_matrix_sync(al, Al + kk * SPK + m0, SPK);
#pragma unroll
            for (int nj = 0; nj < 2; nj++) {
                wmma::mma_sync(acc[mi][nj], ah, bh[nj], acc[mi][nj]);
                wmma::mma_sync(acc[mi][nj], ah, bl[nj], acc[mi][nj]);
                wmma::mma_sync(acc[mi][nj], al, bh[nj], acc[mi][nj]);
            }
        }
    }
}

// ---------------- convert kernels ----------------
__global__ __launch_bounds__(256) void conv_x(const float4* __restrict__ x) {
    size_t i = (size_t)blockIdx.x * 256 + threadIdx.x;   // BL*DDIM/4
    float4 v = x[i];
    __half h[4], l[4];
    split2(v.x, h[0], l[0]); split2(v.y, h[1], l[1]);
    split2(v.z, h[2], l[2]); split2(v.w, h[3], l[3]);
    ((uint2*)g_xh)[i] = *(uint2*)h;
    ((uint2*)g_xl)[i] = *(uint2*)l;
}
__global__ __launch_bounds__(256) void conv_w(const float4* __restrict__ qw,
                                              const float4* __restrict__ kw) {
    size_t i = (size_t)blockIdx.x * 256 + threadIdx.x;   // DDIM*EDIM/4
    const float4* W = blockIdx.y ? kw : qw;
    __half* oh = blockIdx.y ? g_wkh : g_wqh;
    __half* ol = blockIdx.y ? g_wkl : g_wql;
    float4 v = W[i];
    __half h[4], l[4];
    split2(v.x * 256.0f, h[0], l[0]); split2(v.y * 256.0f, h[1], l[1]);
    split2(v.z * 256.0f, h[2], l[2]); split2(v.w * 256.0f, h[3], l[3]);
    ((uint2*)oh)[i] = *(uint2*)h;
    ((uint2*)ol)[i] = *(uint2*)l;
}

// ---------------- proj: grid (4, 256, 2) ----------------
__global__ __launch_bounds__(256, 2) void proj_kernel()
{
    extern __shared__ __align__(16) char dsm[];
    const int tid = threadIdx.x, lane = tid & 31, wid = tid >> 5;
    const int warpM = wid >> 1, warpN = wid & 1;
    const int mBase = blockIdx.y * 128, nBase = blockIdx.x * 64;
    const __half* Ah = g_xh + (size_t)mBase * DDIM;           // [m][k]
    const __half* Al = g_xl + (size_t)mBase * DDIM;
    const __half* Bh = (blockIdx.z ? g_wkh : g_wqh) + nBase;  // [k][n]
    const __half* Bl = (blockIdx.z ? g_wkl : g_wql) + nBase;
    __half* Oh = blockIdx.z ? g_kh : g_qh;
    __half* Ol = blockIdx.z ? g_kl : g_ql;

    const int am0 = tid >> 2, ac0 = (tid & 3) * 8;
    const int am1 = (tid + 256) >> 2, ac1 = ((tid + 256) & 3) * 8;
    const int bk = tid >> 3, bn = (tid & 7) * 8;
    const uint32_t sbase = sptr(dsm);
    const uint32_t dA0a = sbase + (am0 * SPA + ac0) * 2;
    const uint32_t dA0b = sbase + (am1 * SPA + ac1) * 2;
    const uint32_t dB0  = sbase + SBOFF + (bk * SPB + bn) * 2;

    ACC_DECL;
    const int NK = DDIM / 32;
#define PROJ_CP(s, k0)                                                         \
    do {                                                                       \
        CP16(dA0a + (s) * ASTAGE,          Ah + (size_t)am0 * DDIM + (k0) + ac0); \
        CP16(dA0a + (s) * ASTAGE + A_HL,   Al + (size_t)am0 * DDIM + (k0) + ac0); \
        CP16(dA0b + (s) * ASTAGE,          Ah + (size_t)am1 * DDIM + (k0) + ac1); \
        CP16(dA0b + (s) * ASTAGE + A_HL,   Al + (size_t)am1 * DDIM + (k0) + ac1); \
        CP16(dB0 + (s) * BSTAGE,           Bh + (size_t)((k0) + bk) * EDIM + bn); \
        CP16(dB0 + (s) * BSTAGE + B_HL,    Bl + (size_t)((k0) + bk) * EDIM + bn); \
        CP_COMMIT();                                                           \
    } while (0)

    PROJ_CP(0, 0);
    PROJ_CP(1, 32);
    int s = 0, s2 = 2;   // s = t%3, s2 = (t+2)%3
    for (int t = 0; t < NK; t++) {
        if (t == NK - 1) { CP_WAIT0(); } else { CP_WAIT1(); }
        __syncthreads();
        if (t + 2 < NK) PROJ_CP(s2, (t + 2) * 32);
        mma_rowA32((const __half*)(dsm + s * ASTAGE),
                   (const __half*)(dsm + s * ASTAGE + A_HL),
                   (const __half*)(dsm + SBOFF + s * BSTAGE),
                   (const __half*)(dsm + SBOFF + s * BSTAGE + B_HL),
                   acc, warpM, warpN);
        s = (s == 2) ? 0 : s + 1;
        s2 = (s2 == 2) ? 0 : s2 + 1;
    }
#undef PROJ_CP
    __syncthreads();

    // epilogue: v = exp(acc/256)/16, split hi/lo, coalesced write
    float* stage = reinterpret_cast<float*>(dsm) + wid * 256;
    const float ie = 1.0f / 256.0f;
    const int r = lane >> 1, c0 = (lane & 1) * 8;
#pragma unroll
    for (int mi = 0; mi < 2; mi++)
#pragma unroll
        for (int nj = 0; nj < 2; nj++) {
            wmma::store_matrix_sync(stage, acc[mi][nj], 16, wmma::mem_row_major);
            __syncwarp();
            int rg = mBase + warpM * 32 + mi * 16 + r;
            int cg = nBase + warpN * 32 + nj * 16 + c0;
            __half hb[8], lb[8];
#pragma unroll
            for (int j = 0; j < 8; j++) {
                float v = expf(stage[r * 16 + c0 + j] * ie) * 0.0625f;
                split2(v, hb[j], lb[j]);
            }
            *(uint4*)(Oh + (size_t)rg * EDIM + cg) = *(uint4*)hb;
            *(uint4*)(Ol + (size_t)rg * EDIM + cg) = *(uint4*)lb;
            __syncwarp();
        }
}

// ---------------- zc: one warp per row ----------------
__global__ __launch_bounds__(256) void zc_kernel()
{
    int row = (int)((blockIdx.x * 256 + threadIdx.x) >> 5);
    int lane = threadIdx.x & 31;
    const __half2* ph = (const __half2*)(g_qh + (size_t)row * EDIM);
    const __half2* pl = (const __half2*)(g_ql + (size_t)row * EDIM);
    float s = 0.0f;
#pragma unroll
    for (int i = 0; i < 4; i++) {
        float2 h = __half22float2(ph[lane + 32 * i]);
        float2 l = __half22float2(pl[lane + 32 * i]);
        s += (h.x + h.y) + (l.x + l.y);
    }
#pragma unroll
    for (int o = 16; o; o >>= 1) s += __shfl_xor_sync(0xffffffffu, s, o);
    if (lane == 0) g_zc[row] = 4096.0f / (16.0f * s + 1e-8f);
}

// ---------------- kv: grid (16, 2, 8) ----------------
__global__ __launch_bounds__(256, 2) void kv_kernel()
{
    extern __shared__ __align__(16) char dsm[];
    const int tid = threadIdx.x, lane = tid & 31, wid = tid >> 5;
    const int warpM = wid >> 1, warpN = wid & 1;
    const int b = blockIdx.z;
    const int mBase = blockIdx.y * 128;   // e
    const int nBase = blockIdx.x * 64;    // d
    const __half* Ah = g_kh + (size_t)b * LSEQ * EDIM + mBase;  // [k=l][m=e]
    const __half* Al = g_kl + (size_t)b * LSEQ * EDIM + mBase;
    const __half* Bh = g_xh + (size_t)b * LSEQ * DDIM + nBase;  // [k=l][n=d]
    const __half* Bl = g_xl + (size_t)b * LSEQ * DDIM + nBase;

    const int ak0 = tid >> 4, an0 = (tid & 15) * 8;
    const int ak1 = (tid + 256) >> 4, an1 = ((tid + 256) & 15) * 8;
    const int bk = tid >> 3, bn = (tid & 7) * 8;
    const uint32_t sbase = sptr(dsm);
    const uint32_t dA0a = sbase + (ak0 * SPK + an0) * 2;
    const uint32_t dA0b = sbase + (ak1 * SPK + an1) * 2;
    const uint32_t dB0  = sbase + SBOFF_K + (bk * SPB + bn) * 2;

    ACC_DECL;
    const int NK = LSEQ / 32;
#define KV_CP(s, k0)                                                           \
    do {                                                                       \
        CP16(dA0a + (s) * AKSTAGE,         Ah + (size_t)((k0) + ak0) * EDIM + an0); \
        CP16(dA0a + (s) * AKSTAGE + AK_HL, Al + (size_t)((k0) + ak0) * EDIM + an0); \
        CP16(dA0b + (s) * AKSTAGE,         Ah + (size_t)((k0) + ak1) * EDIM + an1); \
        CP16(dA0b + (s) * AKSTAGE + AK_HL, Al + (size_t)((k0) + ak1) * EDIM + an1); \
        CP16(dB0 + (s) * BSTAGE,           Bh + (size_t)((k0) + bk) * DDIM + bn);   \
        CP16(dB0 + (s) * BSTAGE + B_HL,    Bl + (size_t)((k0) + bk) * DDIM + bn);   \
        CP_COMMIT();                                                           \
    } while (0)

    KV_CP(0, 0);
    KV_CP(1, 32);
    int s = 0, s2 = 2;
    for (int t = 0; t < NK; t++) {
        if (t == NK - 1) { CP_WAIT0(); } else { CP_WAIT1(); }
        __syncthreads();
        if (t + 2 < NK) KV_CP(s2, (t + 2) * 32);
        mma_colA32((const __half*)(dsm + s * AKSTAGE),
                   (const __half*)(dsm + s * AKSTAGE + AK_HL),
                   (const __half*)(dsm + SBOFF_K + s * BSTAGE),
                   (const __half*)(dsm + SBOFF_K + s * BSTAGE + B_HL),
                   acc, warpM, warpN);
        s = (s == 2) ? 0 : s + 1;
        s2 = (s2 == 2) ? 0 : s2 + 1;
    }
#undef KV_CP
    __syncthreads();

    // epilogue: kvh/kvl = split(acc/16) = split(kv/256)
    float* stage = reinterpret_cast<float*>(dsm) + wid * 256;
    __half* Oh = g_kvh + (size_t)b * EDIM * DDIM;
    __half* Ol = g_kvl + (size_t)b * EDIM * DDIM;
    const int r = lane >> 1, c0 = (lane & 1) * 8;
#pragma unroll
    for (int mi = 0; mi < 2; mi++)
#pragma unroll
        for (int nj = 0; nj < 2; nj++) {
            wmma::store_matrix_sync(stage, acc[mi][nj], 16, wmma::mem_row_major);
            __syncwarp();
            int rg = mBase + warpM * 32 + mi * 16 + r;
            int cg = nBase + warpN * 32 + nj * 16 + c0;
            __half hb[8], lb[8];
#pragma unroll
            for (int j = 0; j < 8; j++)
                split2(stage[r * 16 + c0 + j] * 0.0625f, hb[j], lb[j]);
            *(uint4*)(Oh + (size_t)rg * DDIM + cg) = *(uint4*)hb;
            *(uint4*)(Ol + (size_t)rg * DDIM + cg) = *(uint4*)lb;
            __syncwarp();
        }
}

// ---------------- num: grid (16, 32, 8) ----------------
__global__ __launch_bounds__(256, 2) void num_kernel(float* __restrict__ out)
{
    extern __shared__ __align__(16) char dsm[];
    const int tid = threadIdx.x, lane = tid & 31, wid = tid >> 5;
    const int warpM = wid >> 1, warpN = wid & 1;
    const int b = blockIdx.z;
    const int mBase = blockIdx.y * 128;   // l
    const int nBase = blockIdx.x * 64;    // d
    const __half* Ah = g_qh + ((size_t)b * LSEQ + mBase) * EDIM;  // [m=l][k=e]
    const __half* Al = g_ql + ((size_t)b * LSEQ + mBase) * EDIM;
    const __half* Bh = g_kvh + (size_t)b * EDIM * DDIM + nBase;   // [k=e][n=d]
    const __half* Bl = g_kvl + (size_t)b * EDIM * DDIM + nBase;

    const int am0 = tid >> 2, ac0 = (tid & 3) * 8;
    const int am1 = (tid + 256) >> 2, ac1 = ((tid + 256) & 3) * 8;
    const int bk = tid >> 3, bn = (tid & 7) * 8;
    const uint32_t sbase = sptr(dsm);
    const uint32_t dA0a = sbase + (am0 * SPA + ac0) * 2;
    const uint32_t dA0b = sbase + (am1 * SPA + ac1) * 2;
    const uint32_t dB0  = sbase + SBOFF + (bk * SPB + bn) * 2;

    ACC_DECL;
    const int NK = EDIM / 32;
#define NUM_CP(s, k0)                                                          \
    do {                                                                       \
        CP16(dA0a + (s) * ASTAGE,          Ah + (size_t)am0 * EDIM + (k0) + ac0); \
        CP16(dA0a + (s) * ASTAGE + A_HL,   Al + (size_t)am0 * EDIM + (k0) + ac0); \
        CP16(dA0b + (s) * ASTAGE,          Ah + (size_t)am1 * EDIM + (k0) + ac1); \
        CP16(dA0b + (s) * ASTAGE + A_HL,   Al + (size_t)am1 * EDIM + (k0) + ac1); \
        CP16(dB0 + (s) * BSTAGE,           Bh + (size_t)((k0) + bk) * DDIM + bn); \
        CP16(dB0 + (s) * BSTAGE + B_HL,    Bl + (size_t)((k0) + bk) * DDIM + bn); \
        CP_COMMIT();                                                           \
    } while (0)

    NUM_CP(0, 0);
    NUM_CP(1, 32);
    int s = 0, s2 = 2;
    for (int t = 0; t < NK; t++) {
        if (t == NK - 1) { CP_WAIT0(); } else { CP_WAIT1(); }
        __syncthreads();
        if (t + 2 < NK) NUM_CP(s2, (t + 2) * 32);
        mma_rowA32((const __half*)(dsm + s * ASTAGE),
                   (const __half*)(dsm + s * ASTAGE + A_HL),
                   (const __half*)(dsm + SBOFF + s * BSTAGE),
                   (const __half*)(dsm + SBOFF + s * BSTAGE + B_HL),
                   acc, warpM, warpN);
        s = (s == 2) ? 0 : s + 1;
        s2 = (s2 == 2) ? 0 : s2 + 1;
    }
#undef NUM_CP
    __syncthreads();

    // epilogue: out = acc * zc[row]
    float* stage = reinterpret_cast<float*>(dsm) + wid * 256;
    float* O = out + (size_t)b * LSEQ * DDIM;
    const int r = lane >> 1, c0 = (lane & 1) * 8;
#pragma unroll
    for (int mi = 0; mi < 2; mi++)
#pragma unroll
        for (int nj = 0; nj < 2; nj++) {
            wmma::store_matrix_sync(stage, acc[mi][nj], 16, wmma::mem_row_major);
            __syncwarp();
            int rg = mBase + warpM * 32 + mi * 16 + r;
            int cg = nBase + warpN * 32 + nj * 16 + c0;
            float zc = g_zc[b * LSEQ + rg];
            float ob[8];
#pragma unroll
            for (int j = 0; j < 8; j++)
                ob[j] = stage[r * 16 + c0 + j] * zc;
            *(float4*)(O + (size_t)rg * DDIM + cg)     = *(float4*)&ob[0];
            *(float4*)(O + (size_t)rg * DDIM + cg + 4) = *(float4*)&ob[4];
            __syncwarp();
        }
}

// ---------------- launch ----------------
extern "C" void kernel_launch(void* const* d_in, const int* in_sizes, int n_in,
                              void* d_out, int out_size)
{
    const float* x  = (const float*)d_in[0];
    const float* qw = (const float*)d_in[1];
    const float* kw = (const float*)d_in[2];
    float* out = (float*)d_out;

    cudaFuncSetAttribute(proj_kernel, cudaFuncAttributeMaxDynamicSharedMemorySize, SMEM_PN);
    cudaFuncSetAttribute(kv_kernel,   cudaFuncAttributeMaxDynamicSharedMemorySize, SMEM_KV);
    cudaFuncSetAttribute(num_kernel,  cudaFuncAttributeMaxDynamicSharedMemorySize, SMEM_PN);

    conv_x<<<(int)((size_t)BL * DDIM / 4 / 256), 256>>>((const float4*)x);
    conv_w<<<dim3(DDIM * EDIM / 4 / 256, 2), 256>>>((const float4*)qw,
                                                    (const float4*)kw);
    proj_kernel<<<dim3(EDIM / 64, BL / 128, 2), 256, SMEM_PN>>>();
    zc_kernel<<<BL / 8, 256>>>();
    kv_kernel<<<dim3(DDIM / 64, EDIM / 128, BATCH), 256, SMEM_KV>>>();
    num_kernel<<<dim3(DDIM / 64, LSEQ / 128, BATCH), 256, SMEM_PN>>>(out);
}

// round 16
// speedup vs baseline: 1.0598x; 1.0005x over previous
#include <cuda_runtime.h>
#include <cuda_fp16.h>
#include <mma.h>
#include <math.h>
#include <stdint.h>

using namespace nvcuda;

// Linear attention, wmma m16n16k16 + 3xFP16 hi/lo splitting.
// R16 = R13 pipeline (BK=32, 2-stage cp.async, 256 thr, 2 CTA/SM, dyn smem)
// with warp tile 32x64 (acc[2][4]) and block tile 256x64: A fragments are
// read by exactly ONE warp (was 2) -> ~25% less smem LDSM traffic, which
// R8/R13 profiles showed as the top pipe (L1 > tensor).
//   conv:  xh/xl = split(x);  wh/wl = split(256*W)
//   proj:  acc = x @ 256W;  qh/ql = split(exp(acc/256)/16) = split(16*q'')
//   zc  :  zc[l] = 4096 / (16*sum(qh+ql) + 1e-8)
//   kv  :  acc = (16k'')^T @ x = kv/16;  kvh/kvl = split(acc/16) = split(kv/256)
//   num :  acc = (16q'') @ (kv/256) = q'*kv/4096;  out = acc * zc[l]

#define BATCH 8
#define LSEQ  4096
#define DDIM  1024
#define EDIM  256
#define BL    (BATCH * LSEQ)
#define SPA   40    // A row-major tile pitch: 32 data + 8 pad halves
#define SPB   72    // B tile pitch: 64 data + 8 pad halves
#define SPK   264   // kv A col-major tile pitch: 256 data + 8 pad halves

// dynamic smem layout (bytes), 2 stages
#define A_HL    (256 * SPA * 2)          // 20480
#define ASTAGE  (2 * A_HL)               // 40960
#define SBOFF   (2 * ASTAGE)             // 81920
#define B_HL    (32 * SPB * 2)           // 4608
#define BSTAGE  (2 * B_HL)               // 9216
#define SMEM_PN (SBOFF + 2 * BSTAGE)     // 100352
#define AK_HL   (32 * SPK * 2)           // 16896
#define AKSTAGE (2 * AK_HL)              // 33792
#define SBOFF_K (2 * AKSTAGE)            // 67584
#define SMEM_KV (SBOFF_K + 2 * BSTAGE)   // 86016

// ---- scratch ----
__device__ __align__(16) __half g_xh[(size_t)BL * DDIM];   // [l][d]
__device__ __align__(16) __half g_xl[(size_t)BL * DDIM];
__device__ __align__(16) __half g_wqh[DDIM * EDIM];        // [d][e], 256W
__device__ __align__(16) __half g_wql[DDIM * EDIM];
__device__ __align__(16) __half g_wkh[DDIM * EDIM];
__device__ __align__(16) __half g_wkl[DDIM * EDIM];
__device__ __align__(16) __half g_qh[(size_t)BL * EDIM];   // [l][e], 16q''
__device__ __align__(16) __half g_ql[(size_t)BL * EDIM];
__device__ __align__(16) __half g_kh[(size_t)BL * EDIM];
__device__ __align__(16) __half g_kl[(size_t)BL * EDIM];
__device__ __align__(16) __half g_kvh[(size_t)BATCH * EDIM * DDIM];  // [b][e][d]
__device__ __align__(16) __half g_kvl[(size_t)BATCH * EDIM * DDIM];
__device__ float g_zc[BL];

// ---------------- helpers ----------------
__device__ __forceinline__ void split2(float x, __half& h, __half& l) {
    h = __float2half_rn(x);
    l = __float2half_rn(x - __half2float(h));
}
__device__ __forceinline__ uint32_t sptr(const void* p) {
    return (uint32_t)__cvta_generic_to_shared(p);
}
#define CP16(dst, src) \
    asm volatile("cp.async.cg.shared.global [%0], [%1], 16;" :: "r"(dst), "l"(src))
#define CP_COMMIT() asm volatile("cp.async.commit_group;")
#define CP_WAIT1()  asm volatile("cp.async.wait_group 1;")
#define CP_WAIT0()  asm volatile("cp.async.wait_group 0;")

#define ACC_DECL                                                               \
    wmma::fragment<wmma::accumulator, 16, 16, 16, float> acc[2][4];            \
    _Pragma("unroll") for (int mi = 0; mi < 2; mi++)                           \
    _Pragma("unroll") for (int nj = 0; nj < 4; nj++)                           \
        wmma::fill_fragment(acc[mi][nj], 0.0f)

// A row-major ([256m][32k] pitch SPA), B ([32k][64n] pitch SPB).
// Warp wid owns rows [wid*32, wid*32+32), full 64-wide N.
__device__ __forceinline__ void mma_rowA32(
    const __half* Ah, const __half* Al, const __half* Bh, const __half* Bl,
    wmma::fragment<wmma::accumulator, 16, 16, 16, float> acc[2][4], int wid)
{
#pragma unroll
    for (int kk = 0; kk < 32; kk += 16) {
        wmma::fragment<wmma::matrix_a, 16, 16, 16, __half, wmma::row_major> ah[2], al[2];
#pragma unroll
        for (int mi = 0; mi < 2; mi++) {
            int m0 = wid * 32 + mi * 16;
            wmma::load_matrix_sync(ah[mi], Ah + m0 * SPA + kk, SPA);
            wmma::load_matrix_sync(al[mi], Al + m0 * SPA + kk, SPA);
        }
#pragma unroll
        for (int nj = 0; nj < 4; nj++) {
            wmma::fragment<wmma::matrix_b, 16, 16, 16, __half, wmma::row_major> bh, bl;
            wmma::load_matrix_sync(bh, Bh + kk * SPB + nj * 16, SPB);
            wmma::load_matrix_sync(bl, Bl + kk * SPB + nj * 16, SPB);
#pragma unroll
            for (int mi = 0; mi < 2; mi++) {
                wmma::mma_sync(acc[mi][nj], ah[mi], bh, acc[mi][nj]);
                wmma::mma_sync(acc[mi][nj], ah[mi], bl, acc[mi][nj]);
                wmma::mma_sync(acc[mi][nj], al[mi], bh, acc[mi][nj]);
            }
        }
    }
}
// A col-major ([32k][256m] pitch SPK)
__device__ __forceinline__ void mma_colA32(
    const __half* Ah, const __half* Al, const __half* Bh, const __half* Bl,
    wmma::fragment<wmma::accumulator, 16, 16, 16, float> acc[2][4], int wid)
{
#pragma unroll
    for (int kk = 0; kk < 32; kk += 16) {
        wmma::fragment<wmma::matrix_a, 16, 16, 16, __half, wmma::col_major> ah[2], al[2];
#pragma unroll
        for (int mi = 0; mi < 2; mi++) {
            int m0 = wid * 32 + mi * 16;
            wmma::load_matrix_sync(ah[mi], Ah + kk * SPK + m0, SPK);
            wmma::load_matrix_sync(al[mi], Al + kk * SPK + m0, SPK);
        }
#pragma unroll
        for (int nj = 0; nj < 4; nj++) {
            wmma::fragment<wmma::matrix_b, 16, 16, 16, __half, wmma::row_major> bh, bl;
            wmma::load_matrix_sync(bh, Bh + kk * SPB + nj * 16, SPB);
            wmma::load_matrix_sync(bl, Bl + kk * SPB + nj * 16, SPB);
#pragma unroll
            for (int mi = 0; mi < 2; mi++) {
                wmma::mma_sync(acc[mi][nj], ah[mi], bh, acc[mi][nj]);
                wmma::mma_sync(acc[mi][nj], ah[mi], bl, acc[mi][nj]);
                wmma::mma_sync(acc[mi][nj], al[mi], bh, acc[mi][nj]);
            }
        }
    }
}

// ---------------- convert kernels ----------------
__global__ __launch_bounds__(256) void conv_x(const float4* __restrict__ x) {
    size_t i = (size_t)blockIdx.x * 256 + threadIdx.x;   // BL*DDIM/4
    float4 v = x[i];
    __half h[4], l[4];
    split2(v.x, h[0], l[0]); split2(v.y, h[1], l[1]);
    split2(v.z, h[2], l[2]); split2(v.w, h[3], l[3]);
    ((uint2*)g_xh)[i] = *(uint2*)h;
    ((uint2*)g_xl)[i] = *(uint2*)l;
}
__global__ __launch_bounds__(256) void conv_w(const float4* __restrict__ qw,
                                              const float4* __restrict__ kw) {
    size_t i = (size_t)blockIdx.x * 256 + threadIdx.x;   // DDIM*EDIM/4
    const float4* W = blockIdx.y ? kw : qw;
    __half* oh = blockIdx.y ? g_wkh : g_wqh;
    __half* ol = blockIdx.y ? g_wkl : g_wql;
    float4 v = W[i];
    __half h[4], l[4];
    split2(v.x * 256.0f, h[0], l[0]); split2(v.y * 256.0f, h[1], l[1]);
    split2(v.z * 256.0f, h[2], l[2]); split2(v.w * 256.0f, h[3], l[3]);
    ((uint2*)oh)[i] = *(uint2*)h;
    ((uint2*)ol)[i] = *(uint2*)l;
}

// ---------------- proj: grid (EDIM/64=4, BL/256=128, 2) ----------------
__global__ __launch_bounds__(256, 2) void proj_kernel()
{
    extern __shared__ __align__(16) char dsm[];
    const int tid = threadIdx.x, lane = tid & 31, wid = tid >> 5;
    const int mBase = blockIdx.y * 256, nBase = blockIdx.x * 64;
    const __half* Ah = g_xh + (size_t)mBase * DDIM;           // [m][k]
    const __half* Al = g_xl + (size_t)mBase * DDIM;
    const __half* Bh = (blockIdx.z ? g_wkh : g_wqh) + nBase;  // [k][n]
    const __half* Bl = (blockIdx.z ? g_wkl : g_wql) + nBase;
    __half* Oh = blockIdx.z ? g_kh : g_qh;
    __half* Ol = blockIdx.z ? g_kl : g_ql;

    // A: 256 rows x 32 halves = 1024 chunks, 4/thread; B: 32x64 = 256 chunks.
    const int bk = tid >> 3, bn = (tid & 7) * 8;
    const uint32_t sbase = sptr(dsm);
    const uint32_t dB0 = sbase + SBOFF + (bk * SPB + bn) * 2;

    ACC_DECL;
    const int NK = DDIM / 32;
#define PROJ_CP(s, k0)                                                         \
    do {                                                                       \
        _Pragma("unroll")                                                      \
        for (int i = 0; i < 4; i++) {                                          \
            int u = tid + i * 256, row = u >> 2, col = (u & 3) * 8;            \
            uint32_t d = sbase + (s) * ASTAGE + (row * SPA + col) * 2;         \
            CP16(d,        Ah + (size_t)row * DDIM + (k0) + col);              \
            CP16(d + A_HL, Al + (size_t)row * DDIM + (k0) + col);              \
        }                                                                      \
        CP16(dB0 + (s) * BSTAGE,        Bh + (size_t)((k0) + bk) * EDIM + bn); \
        CP16(dB0 + (s) * BSTAGE + B_HL, Bl + (size_t)((k0) + bk) * EDIM + bn); \
        CP_COMMIT();                                                           \
    } while (0)

    PROJ_CP(0, 0);
    for (int t = 0; t < NK; t++) {
        if (t + 1 < NK) { PROJ_CP((t + 1) & 1, (t + 1) * 32); CP_WAIT1(); }
        else            { CP_WAIT0(); }
        __syncthreads();
        int s = t & 1;
        mma_rowA32((const __half*)(dsm + s * ASTAGE),
                   (const __half*)(dsm + s * ASTAGE + A_HL),
                   (const __half*)(dsm + SBOFF + s * BSTAGE),
                   (const __half*)(dsm + SBOFF + s * BSTAGE + B_HL),
                   acc, wid);
        __syncthreads();
    }
#undef PROJ_CP

    // epilogue: v = exp(acc/256)/16, split hi/lo, coalesced write
    float* stage = reinterpret_cast<float*>(dsm) + wid * 256;
    const float ie = 1.0f / 256.0f;
    const int r = lane >> 1, c0 = (lane & 1) * 8;
#pragma unroll
    for (int mi = 0; mi < 2; mi++)
#pragma unroll
        for (int nj = 0; nj < 4; nj++) {
            wmma::store_matrix_sync(stage, acc[mi][nj], 16, wmma::mem_row_major);
            __syncwarp();
            int rg = mBase + wid * 32 + mi * 16 + r;
            int cg = nBase + nj * 16 + c0;
            __half hb[8], lb[8];
#pragma unroll
            for (int j = 0; j < 8; j++) {
                float v = expf(stage[r * 16 + c0 + j] * ie) * 0.0625f;
                split2(v, hb[j], lb[j]);
            }
            *(uint4*)(Oh + (size_t)rg * EDIM + cg) = *(uint4*)hb;
            *(uint4*)(Ol + (size_t)rg * EDIM + cg) = *(uint4*)lb;
            __syncwarp();
        }
}

// ---------------- zc: one warp per row ----------------
__global__ __launch_bounds__(256) void zc_kernel()
{
    int row = (int)((blockIdx.x * 256 + threadIdx.x) >> 5);
    int lane = threadIdx.x & 31;
    const __half2* ph = (const __half2*)(g_qh + (size_t)row * EDIM);
    const __half2* pl = (const __half2*)(g_ql + (size_t)row * EDIM);
    float s = 0.0f;
#pragma unroll
    for (int i = 0; i < 4; i++) {
        float2 h = __half22float2(ph[lane + 32 * i]);
        float2 l = __half22float2(pl[lane + 32 * i]);
        s += (h.x + h.y) + (l.x + l.y);
    }
#pragma unroll
    for (int o = 16; o; o >>= 1) s += __shfl_xor_sync(0xffffffffu, s, o);
    if (lane == 0) g_zc[row] = 4096.0f / (16.0f * s + 1e-8f);
}

// ---------------- kv: grid (DDIM/64=16, EDIM/256=1, 8) ----------------
__global__ __launch_bounds__(256, 2) void kv_kernel()
{
    extern __shared__ __align__(16) char dsm[];
    const int tid = threadIdx.x, lane = tid & 31, wid = tid >> 5;
    const int b = blockIdx.z;
    const int mBase = blockIdx.y * 256;   // e
    const int nBase = blockIdx.x * 64;    // d
    const __half* Ah = g_kh + (size_t)b * LSEQ * EDIM + mBase;  // [k=l][m=e]
    const __half* Al = g_kl + (size_t)b * LSEQ * EDIM + mBase;
    const __half* Bh = g_xh + (size_t)b * LSEQ * DDIM + nBase;  // [k=l][n=d]
    const __half* Bl = g_xl + (size_t)b * LSEQ * DDIM + nBase;

    const int bk = tid >> 3, bn = (tid & 7) * 8;
    const uint32_t sbase = sptr(dsm);
    const uint32_t dB0 = sbase + SBOFF_K + (bk * SPB + bn) * 2;

    ACC_DECL;
    const int NK = LSEQ / 32;
#define KV_CP(s, k0)                                                           \
    do {                                                                       \
        _Pragma("unroll")                                                      \
        for (int i = 0; i < 4; i++) {                                          \
            int u = tid + i * 256, row = u >> 5, col = (u & 31) * 8;           \
            uint32_t d = sbase + (s) * AKSTAGE + (row * SPK + col) * 2;        \
            CP16(d,         Ah + (size_t)((k0) + row) * EDIM + col);           \
            CP16(d + AK_HL, Al + (size_t)((k0) + row) * EDIM + col);           \
        }                                                                      \
        CP16(dB0 + (s) * BSTAGE,        Bh + (size_t)((k0) + bk) * DDIM + bn); \
        CP16(dB0 + (s) * BSTAGE + B_HL, Bl + (size_t)((k0) + bk) * DDIM + bn); \
        CP_COMMIT();                                                           \
    } while (0)

    KV_CP(0, 0);
    for (int t = 0; t < NK; t++) {
        if (t + 1 < NK) { KV_CP((t + 1) & 1, (t + 1) * 32); CP_WAIT1(); }
        else            { CP_WAIT0(); }
        __syncthreads();
        int s = t & 1;
        mma_colA32((const __half*)(dsm + s * AKSTAGE),
                   (const __half*)(dsm + s * AKSTAGE + AK_HL),
                   (const __half*)(dsm + SBOFF_K + s * BSTAGE),
                   (const __half*)(dsm + SBOFF_K + s * BSTAGE + B_HL),
                   acc, wid);
        __syncthreads();
    }
#undef KV_CP

    // epilogue: kvh/kvl = split(acc/16) = split(kv/256)
    float* stage = reinterpret_cast<float*>(dsm) + wid * 256;
    __half* Oh = g_kvh + (size_t)b * EDIM * DDIM;
    __half* Ol = g_kvl + (size_t)b * EDIM * DDIM;
    const int r = lane >> 1, c0 = (lane & 1) * 8;
#pragma unroll
    for (int mi = 0; mi < 2; mi++)
#pragma unroll
        for (int nj = 0; nj < 4; nj++) {
            wmma::store_matrix_sync(stage, acc[mi][nj], 16, wmma::mem_row_major);
            __syncwarp();
            int rg = mBase + wid * 32 + mi * 16 + r;
            int cg = nBase + nj * 16 + c0;
            __half hb[8], lb[8];
#pragma unroll
            for (int j = 0; j < 8; j++)
                split2(stage[r * 16 + c0 + j] * 0.0625f, hb[j], lb[j]);
            *(uint4*)(Oh + (size_t)rg * DDIM + cg) = *(uint4*)hb;
            *(uint4*)(Ol + (size_t)rg * DDIM + cg) = *(uint4*)lb;
            __syncwarp();
        }
}

// ---------------- num: grid (16, LSEQ/256=16, 8) ----------------
__global__ __launch_bounds__(256, 2) void num_kernel(float* __restrict__ out)
{
    extern __shared__ __align__(16) char dsm[];
    const int tid = threadIdx.x, lane = tid & 31, wid = tid >> 5;
    const int b = blockIdx.z;
    const int mBase = blockIdx.y * 256;   // l
    const int nBase = blockIdx.x * 64;    // d
    const __half* Ah = g_qh + ((size_t)b * LSEQ + mBase) * EDIM;  // [m=l][k=e]
    const __half* Al = g_ql + ((size_t)b * LSEQ + mBase) * EDIM;
    const __half* Bh = g_kvh + (size_t)b * EDIM * DDIM + nBase;   // [k=e][n=d]
    const __half* Bl = g_kvl + (size_t)b * EDIM * DDIM + nBase;

    const int bk = tid >> 3, bn = (tid & 7) * 8;
    const uint32_t sbase = sptr(dsm);
    const uint32_t dB0 = sbase + SBOFF + (bk * SPB + bn) * 2;

    ACC_DECL;
    const int NK = EDIM / 32;
#define NUM_CP(s, k0)                                                          \
    do {                                                                       \
        _Pragma("unroll")                                                      \
        for (int i = 0; i < 4; i++) {                                          \
            int u = tid + i * 256, row = u >> 2, col = (u & 3) * 8;            \
            uint32_t d = sbase + (s) * ASTAGE + (row * SPA + col) * 2;         \
            CP16(d,        Ah + (size_t)row * EDIM + (k0) + col);              \
            CP16(d + A_HL, Al + (size_t)row * EDIM + (k0) + col);              \
        }                                                                      \
        CP16(dB0 + (s) * BSTAGE,        Bh + (size_t)((k0) + bk) * DDIM + bn); \
        CP16(dB0 + (s) * BSTAGE + B_HL, Bl + (size_t)((k0) + bk) * DDIM + bn); \
        CP_COMMIT();                                                           \
    } while (0)

    NUM_CP(0, 0);
    for (int t = 0; t < NK; t++) {
        if (t + 1 < NK) { NUM_CP((t + 1) & 1, (t + 1) * 32); CP_WAIT1(); }
        else            { CP_WAIT0(); }
        __syncthreads();
        int s = t & 1;
        mma_rowA32((const __half*)(dsm + s * ASTAGE),
                   (const __half*)(dsm + s * ASTAGE + A_HL),
                   (const __half*)(dsm + SBOFF + s * BSTAGE),
                   (const __half*)(dsm + SBOFF + s * BSTAGE + B_HL),
                   acc, wid);
        __syncthreads();
    }
#undef NUM_CP

    // epilogue: out = acc * zc[row]
    float* stage = reinterpret_cast<float*>(dsm) + wid * 256;
    float* O = out + (size_t)b * LSEQ * DDIM;
    const int r = lane >> 1, c0 = (lane & 1) * 8;
#pragma unroll
    for (int mi = 0; mi < 2; mi++)
#pragma unroll
        for (int nj = 0; nj < 4; nj++) {
            wmma::store_matrix_sync(stage, acc[mi][nj], 16, wmma::mem_row_major);
            __syncwarp();
            int rg = mBase + wid * 32 + mi * 16 + r;
            int cg = nBase + nj * 16 + c0;
            float zc = g_zc[b * LSEQ + rg];
            float ob[8];
#pragma unroll
            for (int j = 0; j < 8; j++)
                ob[j] = stage[r * 16 + c0 + j] * zc;
            *(float4*)(O + (size_t)rg * DDIM + cg)     = *(float4*)&ob[0];
            *(float4*)(O + (size_t)rg * DDIM + cg + 4) = *(float4*)&ob[4];
            __syncwarp();
        }
}

// ---------------- launch ----------------
extern "C" void kernel_launch(void* const* d_in, const int* in_sizes, int n_in,
                              void* d_out, int out_size)
{
    const float* x  = (const float*)d_in[0];
    const float* qw = (const float*)d_in[1];
    const float* kw = (const float*)d_in[2];
    float* out = (float*)d_out;

    cudaFuncSetAttribute(proj_kernel, cudaFuncAttributeMaxDynamicSharedMemorySize, SMEM_PN);
    cudaFuncSetAttribute(kv_kernel,   cudaFuncAttributeMaxDynamicSharedMemorySize, SMEM_KV);
    cudaFuncSetAttribute(num_kernel,  cudaFuncAttributeMaxDynamicSharedMemorySize, SMEM_PN);

    conv_x<<<(int)((size_t)BL * DDIM / 4 / 256), 256>>>((const float4*)x);
    conv_w<<<dim3(DDIM * EDIM / 4 / 256, 2), 256>>>((const float4*)qw,
                                                    (const float4*)kw);
    proj_kernel<<<dim3(EDIM / 64, BL / 256, 2), 256, SMEM_PN>>>();
    zc_kernel<<<BL / 8, 256>>>();
    kv_kernel<<<dim3(DDIM / 64, EDIM / 256, BATCH), 256, SMEM_KV>>>();
    num_kernel<<<dim3(DDIM / 64, LSEQ / 256, BATCH), 256, SMEM_PN>>>(out);
}

// round 17
// speedup vs baseline: 1.2103x; 1.1420x over previous
#include <cuda_runtime.h>
#include <cuda_fp16.h>
#include <mma.h>
#include <math.h>
#include <stdint.h>

using namespace nvcuda;

// Linear attention, wmma m16n16k16 + error-compensated fp16 splitting.
// R17 = R13 base, spending precision margin (rel_err 4e-5 vs 1e-3 threshold):
//   proj: 3 passes (unchanged — feeds exp, needs accuracy)
//   kv  : 2 passes  kh*xh + kh*xl   (k-lo correction dropped; g_kl dead)
//   num : 2 passes  qh*kvh + ql*kvh (kv-lo correction dropped; g_kvl dead)
// Predicted added error ~2.4e-4 per dropped pass; total ~3-5e-4 < 1e-3.
//   conv:  xh/xl = split(x);  wh/wl = split(256*W)
//   proj:  acc = x @ 256W;  qh/ql = split(exp(acc/256)/16); k: hi only
//   zc  :  zc[l] = 4096 / (16*sum(qh+ql) + 1e-8)
//   kv  :  acc = (16kh)^T @ x = ~kv/16;  kvh = fp16(acc/16) = ~kv/256
//   num :  acc = (16q'') @ kvh = ~q'*kv/4096;  out = acc * zc[l]

#define BATCH 8
#define LSEQ  4096
#define DDIM  1024
#define EDIM  256
#define BL    (BATCH * LSEQ)
#define SPA   40    // A row-major tile pitch: 32 data + 8 pad halves
#define SPB   72    // B tile pitch: 64 data + 8 pad halves
#define SPK   136   // kv A col-major tile pitch: 128 data + 8 pad halves

// dynamic smem layouts (bytes)
#define A_HL     (128 * SPA * 2)           // 10240
#define ASTAGE   (2 * A_HL)                // 20480 (hi+lo)
#define SBOFF    (2 * ASTAGE)              // 40960
#define B_HL     (32 * SPB * 2)            // 4608
#define BSTAGE   (2 * B_HL)                // 9216 (hi+lo)
#define SMEM_PROJ (SBOFF + 2 * BSTAGE)     // 59392
#define SMEM_NUM  (SBOFF + 2 * B_HL)       // 50176 (B hi only)
#define AK_HL    (32 * SPK * 2)            // 8704 (hi only per stage)
#define SBOFF_K  (2 * AK_HL)               // 17408
#define SMEM_KV  (SBOFF_K + 2 * BSTAGE)    // 35840

// ---- scratch ----
__device__ __align__(16) __half g_xh[(size_t)BL * DDIM];   // [l][d]
__device__ __align__(16) __half g_xl[(size_t)BL * DDIM];
__device__ __align__(16) __half g_wqh[DDIM * EDIM];        // [d][e], 256W
__device__ __align__(16) __half g_wql[DDIM * EDIM];
__device__ __align__(16) __half g_wkh[DDIM * EDIM];
__device__ __align__(16) __half g_wkl[DDIM * EDIM];
__device__ __align__(16) __half g_qh[(size_t)BL * EDIM];   // [l][e], 16q''
__device__ __align__(16) __half g_ql[(size_t)BL * EDIM];
__device__ __align__(16) __half g_kh[(size_t)BL * EDIM];   // hi only used
__device__ __align__(16) __half g_kvh[(size_t)BATCH * EDIM * DDIM];  // [b][e][d]
__device__ float g_zc[BL];

// ---------------- helpers ----------------
__device__ __forceinline__ void split2(float x, __half& h, __half& l) {
    h = __float2half_rn(x);
    l = __float2half_rn(x - __half2float(h));
}
__device__ __forceinline__ uint32_t sptr(const void* p) {
    return (uint32_t)__cvta_generic_to_shared(p);
}
#define CP16(dst, src) \
    asm volatile("cp.async.cg.shared.global [%0], [%1], 16;" :: "r"(dst), "l"(src))
#define CP_COMMIT() asm volatile("cp.async.commit_group;")
#define CP_WAIT1()  asm volatile("cp.async.wait_group 1;")
#define CP_WAIT0()  asm volatile("cp.async.wait_group 0;")

#define ACC_DECL                                                               \
    wmma::fragment<wmma::accumulator, 16, 16, 16, float> acc[2][2];            \
    _Pragma("unroll") for (int mi = 0; mi < 2; mi++)                           \
    _Pragma("unroll") for (int nj = 0; nj < 2; nj++)                           \
        wmma::fill_fragment(acc[mi][nj], 0.0f)

// proj: 3 passes, A row-major hi+lo, B hi+lo
__device__ __forceinline__ void mma_rowA32_3(
    const __half* Ah, const __half* Al, const __half* Bh, const __half* Bl,
    wmma::fragment<wmma::accumulator, 16, 16, 16, float> acc[2][2],
    int warpM, int warpN)
{
#pragma unroll
    for (int kk = 0; kk < 32; kk += 16) {
        wmma::fragment<wmma::matrix_b, 16, 16, 16, __half, wmma::row_major> bh[2], bl[2];
#pragma unroll
        for (int nj = 0; nj < 2; nj++) {
            int n0 = warpN * 32 + nj * 16;
            wmma::load_matrix_sync(bh[nj], Bh + kk * SPB + n0, SPB);
            wmma::load_matrix_sync(bl[nj], Bl + kk * SPB + n0, SPB);
        }
#pragma unroll
        for (int mi = 0; mi < 2; mi++) {
            int m0 = warpM * 32 + mi * 16;
            wmma::fragment<wmma::matrix_a, 16, 16, 16, __half, wmma::row_major> ah, al;
            wmma::load_matrix_sync(ah, Ah + m0 * SPA + kk, SPA);
            wmma::load_matrix_sync(al, Al + m0 * SPA + kk, SPA);
#pragma unroll
            for (int nj = 0; nj < 2; nj++) {
                wmma::mma_sync(acc[mi][nj], ah, bh[nj], acc[mi][nj]);
                wmma::mma_sync(acc[mi][nj], ah, bl[nj], acc[mi][nj]);
                wmma::mma_sync(acc[mi][nj], al, bh[nj], acc[mi][nj]);
            }
        }
    }
}
// num: 2 passes, A row-major hi+lo, B hi only (ah*bh + al*bh)
__device__ __forceinline__ void mma_rowA32_2A(
    const __half* Ah, const __half* Al, const __half* Bh,
    wmma::fragment<wmma::accumulator, 16, 16, 16, float> acc[2][2],
    int warpM, int warpN)
{
#pragma unroll
    for (int kk = 0; kk < 32; kk += 16) {
        wmma::fragment<wmma::matrix_b, 16, 16, 16, __half, wmma::row_major> bh[2];
#pragma unroll
        for (int nj = 0; nj < 2; nj++)
            wmma::load_matrix_sync(bh[nj], Bh + kk * SPB + warpN * 32 + nj * 16, SPB);
#pragma unroll
        for (int mi = 0; mi < 2; mi++) {
            int m0 = warpM * 32 + mi * 16;
            wmma::fragment<wmma::matrix_a, 16, 16, 16, __half, wmma::row_major> ah, al;
            wmma::load_matrix_sync(ah, Ah + m0 * SPA + kk, SPA);
            wmma::load_matrix_sync(al, Al + m0 * SPA + kk, SPA);
#pragma unroll
            for (int nj = 0; nj < 2; nj++) {
                wmma::mma_sync(acc[mi][nj], ah, bh[nj], acc[mi][nj]);
                wmma::mma_sync(acc[mi][nj], al, bh[nj], acc[mi][nj]);
            }
        }
    }
}
// kv: 2 passes, A col-major hi only, B hi+lo (ah*bh + ah*bl)
__device__ __forceinline__ void mma_colA32_2B(
    const __half* Ah, const __half* Bh, const __half* Bl,
    wmma::fragment<wmma::accumulator, 16, 16, 16, float> acc[2][2],
    int warpM, int warpN)
{
#pragma unroll
    for (int kk = 0; kk < 32; kk += 16) {
        wmma::fragment<wmma::matrix_b, 16, 16, 16, __half, wmma::row_major> bh[2], bl[2];
#pragma unroll
        for (int nj = 0; nj < 2; nj++) {
            int n0 = warpN * 32 + nj * 16;
            wmma::load_matrix_sync(bh[nj], Bh + kk * SPB + n0, SPB);
            wmma::load_matrix_sync(bl[nj], Bl + kk * SPB + n0, SPB);
        }
#pragma unroll
        for (int mi = 0; mi < 2; mi++) {
            wmma::fragment<wmma::matrix_a, 16, 16, 16, __half, wmma::col_major> ah;
            wmma::load_matrix_sync(ah, Ah + kk * SPK + warpM * 32 + mi * 16, SPK);
#pragma unroll
            for (int nj = 0; nj < 2; nj++) {
                wmma::mma_sync(acc[mi][nj], ah, bh[nj], acc[mi][nj]);
                wmma::mma_sync(acc[mi][nj], ah, bl[nj], acc[mi][nj]);
            }
        }
    }
}

// ---------------- convert kernels ----------------
__global__ __launch_bounds__(256) void conv_x(const float4* __restrict__ x) {
    size_t i = (size_t)blockIdx.x * 256 + threadIdx.x;   // BL*DDIM/4
    float4 v = x[i];
    __half h[4], l[4];
    split2(v.x, h[0], l[0]); split2(v.y, h[1], l[1]);
    split2(v.z, h[2], l[2]); split2(v.w, h[3], l[3]);
    ((uint2*)g_xh)[i] = *(uint2*)h;
    ((uint2*)g_xl)[i] = *(uint2*)l;
}
__global__ __launch_bounds__(256) void conv_w(const float4* __restrict__ qw,
                                              const float4* __restrict__ kw) {
    size_t i = (size_t)blockIdx.x * 256 + threadIdx.x;   // DDIM*EDIM/4
    const float4* W = blockIdx.y ? kw : qw;
    __half* oh = blockIdx.y ? g_wkh : g_wqh;
    __half* ol = blockIdx.y ? g_wkl : g_wql;
    float4 v = W[i];
    __half h[4], l[4];
    split2(v.x * 256.0f, h[0], l[0]); split2(v.y * 256.0f, h[1], l[1]);
    split2(v.z * 256.0f, h[2], l[2]); split2(v.w * 256.0f, h[3], l[3]);
    ((uint2*)oh)[i] = *(uint2*)h;
    ((uint2*)ol)[i] = *(uint2*)l;
}

// ---------------- proj: grid (4, 256, 2) ----------------
__global__ __launch_bounds__(256, 2) void proj_kernel()
{
    extern __shared__ __align__(16) char dsm[];
    const int tid = threadIdx.x, lane = tid & 31, wid = tid >> 5;
    const int warpM = wid >> 1, warpN = wid & 1;
    const int mBase = blockIdx.y * 128, nBase = blockIdx.x * 64;
    const int sel = blockIdx.z;
    const __half* Ah = g_xh + (size_t)mBase * DDIM;      // [m][k]
    const __half* Al = g_xl + (size_t)mBase * DDIM;
    const __half* Bh = (sel ? g_wkh : g_wqh) + nBase;    // [k][n]
    const __half* Bl = (sel ? g_wkl : g_wql) + nBase;
    __half* Oh = sel ? g_kh : g_qh;

    const int am0 = tid >> 2, ac0 = (tid & 3) * 8;
    const int am1 = (tid + 256) >> 2, ac1 = ((tid + 256) & 3) * 8;
    const int bk = tid >> 3, bn = (tid & 7) * 8;
    const uint32_t sbase = sptr(dsm);
    const uint32_t dA0a = sbase + (am0 * SPA + ac0) * 2;
    const uint32_t dA0b = sbase + (am1 * SPA + ac1) * 2;
    const uint32_t dB0  = sbase + SBOFF + (bk * SPB + bn) * 2;

    ACC_DECL;
    const int NK = DDIM / 32;
#define PROJ_CP(s, k0)                                                         \
    do {                                                                       \
        CP16(dA0a + (s) * ASTAGE,          Ah + (size_t)am0 * DDIM + (k0) + ac0); \
        CP16(dA0a + (s) * ASTAGE + A_HL,   Al + (size_t)am0 * DDIM + (k0) + ac0); \
        CP16(dA0b + (s) * ASTAGE,          Ah + (size_t)am1 * DDIM + (k0) + ac1); \
        CP16(dA0b + (s) * ASTAGE + A_HL,   Al + (size_t)am1 * DDIM + (k0) + ac1); \
        CP16(dB0 + (s) * BSTAGE,           Bh + (size_t)((k0) + bk) * EDIM + bn); \
        CP16(dB0 + (s) * BSTAGE + B_HL,    Bl + (size_t)((k0) + bk) * EDIM + bn); \
        CP_COMMIT();                                                           \
    } while (0)

    PROJ_CP(0, 0);
    for (int t = 0; t < NK; t++) {
        if (t + 1 < NK) { PROJ_CP((t + 1) & 1, (t + 1) * 32); CP_WAIT1(); }
        else            { CP_WAIT0(); }
        __syncthreads();
        int s = t & 1;
        mma_rowA32_3((const __half*)(dsm + s * ASTAGE),
                     (const __half*)(dsm + s * ASTAGE + A_HL),
                     (const __half*)(dsm + SBOFF + s * BSTAGE),
                     (const __half*)(dsm + SBOFF + s * BSTAGE + B_HL),
                     acc, warpM, warpN);
        __syncthreads();
    }
#undef PROJ_CP

    // epilogue: v = exp(acc/256)/16, hi always; lo only for q (zc + num need it)
    float* stage = reinterpret_cast<float*>(dsm) + wid * 256;
    const float ie = 1.0f / 256.0f;
    const int r = lane >> 1, c0 = (lane & 1) * 8;
#pragma unroll
    for (int mi = 0; mi < 2; mi++)
#pragma unroll
        for (int nj = 0; nj < 2; nj++) {
            wmma::store_matrix_sync(stage, acc[mi][nj], 16, wmma::mem_row_major);
            __syncwarp();
            int rg = mBase + warpM * 32 + mi * 16 + r;
            int cg = nBase + warpN * 32 + nj * 16 + c0;
            __half hb[8], lb[8];
#pragma unroll
            for (int j = 0; j < 8; j++) {
                float v = expf(stage[r * 16 + c0 + j] * ie) * 0.0625f;
                split2(v, hb[j], lb[j]);
            }
            *(uint4*)(Oh + (size_t)rg * EDIM + cg) = *(uint4*)hb;
            if (sel == 0)
                *(uint4*)(g_ql + (size_t)rg * EDIM + cg) = *(uint4*)lb;
            __syncwarp();
        }
}

// ---------------- zc: one warp per row ----------------
__global__ __launch_bounds__(256) void zc_kernel()
{
    int row = (int)((blockIdx.x * 256 + threadIdx.x) >> 5);
    int lane = threadIdx.x & 31;
    const __half2* ph = (const __half2*)(g_qh + (size_t)row * EDIM);
    const __half2* pl = (const __half2*)(g_ql + (size_t)row * EDIM);
    float s = 0.0f;
#pragma unroll
    for (int i = 0; i < 4; i++) {
        float2 h = __half22float2(ph[lane + 32 * i]);
        float2 l = __half22float2(pl[lane + 32 * i]);
        s += (h.x + h.y) + (l.x + l.y);
    }
#pragma unroll
    for (int o = 16; o; o >>= 1) s += __shfl_xor_sync(0xffffffffu, s, o);
    if (lane == 0) g_zc[row] = 4096.0f / (16.0f * s + 1e-8f);
}

// ---------------- kv: grid (16, 2, 8), A hi only ----------------
__global__ __launch_bounds__(256, 2) void kv_kernel()
{
    extern __shared__ __align__(16) char dsm[];
    const int tid = threadIdx.x, lane = tid & 31, wid = tid >> 5;
    const int warpM = wid >> 1, warpN = wid & 1;
    const int b = blockIdx.z;
    const int mBase = blockIdx.y * 128;   // e
    const int nBase = blockIdx.x * 64;    // d
    const __half* Ah = g_kh + (size_t)b * LSEQ * EDIM + mBase;  // [k=l][m=e]
    const __half* Bh = g_xh + (size_t)b * LSEQ * DDIM + nBase;  // [k=l][n=d]
    const __half* Bl = g_xl + (size_t)b * LSEQ * DDIM + nBase;

    const int ak0 = tid >> 4, an0 = (tid & 15) * 8;
    const int ak1 = (tid + 256) >> 4, an1 = ((tid + 256) & 15) * 8;
    const int bk = tid >> 3, bn = (tid & 7) * 8;
    const uint32_t sbase = sptr(dsm);
    const uint32_t dA0a = sbase + (ak0 * SPK + an0) * 2;
    const uint32_t dA0b = sbase + (ak1 * SPK + an1) * 2;
    const uint32_t dB0  = sbase + SBOFF_K + (bk * SPB + bn) * 2;

    ACC_DECL;
    const int NK = LSEQ / 32;
#define KV_CP(s, k0)                                                           \
    do {                                                                       \
        CP16(dA0a + (s) * AK_HL,  Ah + (size_t)((k0) + ak0) * EDIM + an0);     \
        CP16(dA0b + (s) * AK_HL,  Ah + (size_t)((k0) + ak1) * EDIM + an1);     \
        CP16(dB0 + (s) * BSTAGE,          Bh + (size_t)((k0) + bk) * DDIM + bn); \
        CP16(dB0 + (s) * BSTAGE + B_HL,   Bl + (size_t)((k0) + bk) * DDIM + bn); \
        CP_COMMIT();                                                           \
    } while (0)

    KV_CP(0, 0);
    for (int t = 0; t < NK; t++) {
        if (t + 1 < NK) { KV_CP((t + 1) & 1, (t + 1) * 32); CP_WAIT1(); }
        else            { CP_WAIT0(); }
        __syncthreads();
        int s = t & 1;
        mma_colA32_2B((const __half*)(dsm + s * AK_HL),
                      (const __half*)(dsm + SBOFF_K + s * BSTAGE),
                      (const __half*)(dsm + SBOFF_K + s * BSTAGE + B_HL),
                      acc, warpM, warpN);
        __syncthreads();
    }
#undef KV_CP

    // epilogue: kvh = fp16(acc/16) = ~kv/256 (no lo)
    float* stage = reinterpret_cast<float*>(dsm) + wid * 256;
    __half* Oh = g_kvh + (size_t)b * EDIM * DDIM;
    const int r = lane >> 1, c0 = (lane & 1) * 8;
#pragma unroll
    for (int mi = 0; mi < 2; mi++)
#pragma unroll
        for (int nj = 0; nj < 2; nj++) {
            wmma::store_matrix_sync(stage, acc[mi][nj], 16, wmma::mem_row_major);
            __syncwarp();
            int rg = mBase + warpM * 32 + mi * 16 + r;
            int cg = nBase + warpN * 32 + nj * 16 + c0;
            __half hb[8];
#pragma unroll
            for (int j = 0; j < 8; j++)
                hb[j] = __float2half_rn(stage[r * 16 + c0 + j] * 0.0625f);
            *(uint4*)(Oh + (size_t)rg * DDIM + cg) = *(uint4*)hb;
            __syncwarp();
        }
}

// ---------------- num: grid (16, 32, 8), B hi only ----------------
__global__ __launch_bounds__(256, 2) void num_kernel(float* __restrict__ out)
{
    extern __shared__ __align__(16) char dsm[];
    const int tid = threadIdx.x, lane = tid & 31, wid = tid >> 5;
    const int warpM = wid >> 1, warpN = wid & 1;
    const int b = blockIdx.z;
    const int mBase = blockIdx.y * 128;   // l
    const int nBase = blockIdx.x * 64;    // d
    const __half* Ah = g_qh + ((size_t)b * LSEQ + mBase) * EDIM;  // [m=l][k=e]
    const __half* Al = g_ql + ((size_t)b * LSEQ + mBase) * EDIM;
    const __half* Bh = g_kvh + (size_t)b * EDIM * DDIM + nBase;   // [k=e][n=d]

    const int am0 = tid >> 2, ac0 = (tid & 3) * 8;
    const int am1 = (tid + 256) >> 2, ac1 = ((tid + 256) & 3) * 8;
    const int bk = tid >> 3, bn = (tid & 7) * 8;
    const uint32_t sbase = sptr(dsm);
    const uint32_t dA0a = sbase + (am0 * SPA + ac0) * 2;
    const uint32_t dA0b = sbase + (am1 * SPA + ac1) * 2;
    const uint32_t dB0  = sbase + SBOFF + (bk * SPB + bn) * 2;

    ACC_DECL;
    const int NK = EDIM / 32;
#define NUM_CP(s, k0)                                                          \
    do {                                                                       \
        CP16(dA0a + (s) * ASTAGE,          Ah + (size_t)am0 * EDIM + (k0) + ac0); \
        CP16(dA0a + (s) * ASTAGE + A_HL,   Al + (size_t)am0 * EDIM + (k0) + ac0); \
        CP16(dA0b + (s) * ASTAGE,          Ah + (size_t)am1 * EDIM + (k0) + ac1); \
        CP16(dA0b + (s) * ASTAGE + A_HL,   Al + (size_t)am1 * EDIM + (k0) + ac1); \
        CP16(dB0 + (s) * B_HL,             Bh + (size_t)((k0) + bk) * DDIM + bn); \
        CP_COMMIT();                                                           \
    } while (0)

    NUM_CP(0, 0);
    for (int t = 0; t < NK; t++) {
        if (t + 1 < NK) { NUM_CP((t + 1) & 1, (t + 1) * 32); CP_WAIT1(); }
        else            { CP_WAIT0(); }
        __syncthreads();
        int s = t & 1;
        mma_rowA32_2A((const __half*)(dsm + s * ASTAGE),
                      (const __half*)(dsm + s * ASTAGE + A_HL),
                      (const __half*)(dsm + SBOFF + s * B_HL),
                      acc, warpM, warpN);
        __syncthreads();
    }
#undef NUM_CP

    // epilogue: out = acc * zc[row]
    float* stage = reinterpret_cast<float*>(dsm) + wid * 256;
    float* O = out + (size_t)b * LSEQ * DDIM;
    const int r = lane >> 1, c0 = (lane & 1) * 8;
#pragma unroll
    for (int mi = 0; mi < 2; mi++)
#pragma unroll
        for (int nj = 0; nj < 2; nj++) {
            wmma::store_matrix_sync(stage, acc[mi][nj], 16, wmma::mem_row_major);
            __syncwarp();
            int rg = mBase + warpM * 32 + mi * 16 + r;
            int cg = nBase + warpN * 32 + nj * 16 + c0;
            float zc = g_zc[b * LSEQ + rg];
            float ob[8];
#pragma unroll
            for (int j = 0; j < 8; j++)
                ob[j] = stage[r * 16 + c0 + j] * zc;
            *(float4*)(O + (size_t)rg * DDIM + cg)     = *(float4*)&ob[0];
            *(float4*)(O + (size_t)rg * DDIM + cg + 4) = *(float4*)&ob[4];
            __syncwarp();
        }
}

// ---------------- launch ----------------
extern "C" void kernel_launch(void* const* d_in, const int* in_sizes, int n_in,
                              void* d_out, int out_size)
{
    const float* x  = (const float*)d_in[0];
    const float* qw = (const float*)d_in[1];
    const float* kw = (const float*)d_in[2];
    float* out = (float*)d_out;

    cudaFuncSetAttribute(proj_kernel, cudaFuncAttributeMaxDynamicSharedMemorySize, SMEM_PROJ);
    cudaFuncSetAttribute(kv_kernel,   cudaFuncAttributeMaxDynamicSharedMemorySize, SMEM_KV);
    cudaFuncSetAttribute(num_kernel,  cudaFuncAttributeMaxDynamicSharedMemorySize, SMEM_NUM);

    conv_x<<<(int)((size_t)BL * DDIM / 4 / 256), 256>>>((const float4*)x);
    conv_w<<<dim3(DDIM * EDIM / 4 / 256, 2), 256>>>((const float4*)qw,
                                                    (const float4*)kw);
    proj_kernel<<<dim3(EDIM / 64, BL / 128, 2), 256, SMEM_PROJ>>>();
    zc_kernel<<<BL / 8, 256>>>();
    kv_kernel<<<dim3(DDIM / 64, EDIM / 128, BATCH), 256, SMEM_KV>>>();
    num_kernel<<<dim3(DDIM / 64, LSEQ / 128, BATCH), 256, SMEM_NUM>>>(out);
}